// round 5
// baseline (speedup 1.0000x reference)
#include <cuda_runtime.h>
#include <cstdint>

#define NMAX 50048
#define EMAX 1000000
#define FD 128     // H*F_OUT == F_IN == 128
#define HH 8       // heads
#define SB 1024    // scan block size

// Scratch (static __device__ — no allocations allowed)
__device__ float g_xp[(size_t)NMAX * FD];      // x @ W            [N,128]
__device__ float g_asrc[(size_t)NMAX * HH];    // a_src            [N,8]
__device__ float g_adst[(size_t)NMAX * HH];    // a_dst            [N,8]
__device__ int   g_cnt[NMAX + 1];              // per-dst degree
__device__ int   g_rowstart[NMAX + 1];         // CSR row offsets
__device__ int   g_cursor[NMAX];               // scatter cursors
__device__ int   g_csr[EMAX];                  // src indices, grouped by dst

// ---------------------------------------------------------------------------
// xp = x @ W  (+ fused per-node attention logits a_src, a_dst)
// ---------------------------------------------------------------------------
__global__ void gemm_kernel(const float* __restrict__ x,
                            const float* __restrict__ W,
                            const float* __restrict__ att_src,
                            const float* __restrict__ att_dst,
                            int n) {
    __shared__ float4 xs4[32 * 32];           // 32 rows x 32 float4
    const int c  = threadIdx.x;               // output column 0..127
    const int r0 = blockIdx.x * 32;
    const int rows = min(32, n - r0);

    const float4* x4 = (const float4*)x;
    for (int i = threadIdx.x; i < rows * 32; i += 128) {
        int r = i >> 5, k4 = i & 31;
        xs4[r * 32 + k4] = x4[(size_t)(r0 + r) * 32 + k4];
    }
    __syncthreads();

    float acc[32];
#pragma unroll
    for (int r = 0; r < 32; r++) acc[r] = 0.f;

#pragma unroll 4
    for (int k4 = 0; k4 < 32; k4++) {
        float w0 = W[(k4 * 4 + 0) * FD + c];
        float w1 = W[(k4 * 4 + 1) * FD + c];
        float w2 = W[(k4 * 4 + 2) * FD + c];
        float w3 = W[(k4 * 4 + 3) * FD + c];
#pragma unroll
        for (int r = 0; r < 32; r++) {
            float4 xv = xs4[r * 32 + k4];     // broadcast LDS.128
            acc[r] = fmaf(xv.x, w0, acc[r]);
            acc[r] = fmaf(xv.y, w1, acc[r]);
            acc[r] = fmaf(xv.z, w2, acc[r]);
            acc[r] = fmaf(xv.w, w3, acc[r]);
        }
    }

    const float a_s = att_src[c];
    const float a_d = att_dst[c];
    const int lane = threadIdx.x & 31;
    for (int r = 0; r < rows; r++) {
        float v = acc[r];
        g_xp[(size_t)(r0 + r) * FD + c] = v;
        float vs = v * a_s, vd = v * a_d;
#pragma unroll
        for (int off = 8; off; off >>= 1) {
            vs += __shfl_xor_sync(0xffffffffu, vs, off, 16);
            vd += __shfl_xor_sync(0xffffffffu, vd, off, 16);
        }
        if ((lane & 15) == 0) {
            int h = c >> 4;
            g_asrc[(size_t)(r0 + r) * HH + h] = vs;
            g_adst[(size_t)(r0 + r) * HH + h] = vd;
        }
    }
}

// ---------------------------------------------------------------------------
// CSR build
// ---------------------------------------------------------------------------
__global__ void zerocnt_kernel(int n) {
    int i = blockIdx.x * blockDim.x + threadIdx.x;
    if (i <= n) g_cnt[i] = 0;
}

// 2 edges per thread
__global__ void hist_kernel(const int* __restrict__ ei, int E) {
    int t = blockIdx.x * blockDim.x + threadIdx.x;
    int e = t * 2;
    if (e + 1 < E) {
        int2 d = *(const int2*)&ei[E + e];
        atomicAdd(&g_cnt[d.x], 1);
        atomicAdd(&g_cnt[d.y], 1);
    } else if (e < E) {
        atomicAdd(&g_cnt[ei[E + e]], 1);
    }
}

// Single-block exclusive scan: g_cnt[0..n-1] -> g_rowstart[0..n] (+cursor)
__global__ void scan_kernel(int n) {
    const int t = threadIdx.x;
    const int per = (n + SB - 1) / SB;
    const int beg = min(t * per, n);
    const int fin = min(beg + per, n);

    int sum = 0;
    for (int i = beg; i < fin; i++) sum += g_cnt[i];

    const int lane = t & 31, wid = t >> 5;
    int xv = sum;
#pragma unroll
    for (int off = 1; off < 32; off <<= 1) {
        int y = __shfl_up_sync(0xffffffffu, xv, off);
        if (lane >= off) xv += y;
    }
    __shared__ int ws[32];
    if (lane == 31) ws[wid] = xv;
    __syncthreads();
    if (wid == 0) {
        int s = ws[lane];
#pragma unroll
        for (int off = 1; off < 32; off <<= 1) {
            int y = __shfl_up_sync(0xffffffffu, s, off);
            if (lane >= off) s += y;
        }
        ws[lane] = s;
    }
    __syncthreads();
    int run = xv - sum + (wid ? ws[wid - 1] : 0);   // exclusive offset

    for (int i = beg; i < fin; i++) {
        g_rowstart[i] = run;
        g_cursor[i]   = run;
        run += g_cnt[i];
    }
    if (t == 0) g_rowstart[n] = ws[31];             // grand total
}

// 2 edges per thread
__global__ void scatter_kernel(const int* __restrict__ ei, int E) {
    int t = blockIdx.x * blockDim.x + threadIdx.x;
    int e = t * 2;
    if (e + 1 < E) {
        int2 s = *(const int2*)&ei[e];
        int2 d = *(const int2*)&ei[E + e];
        int p0 = atomicAdd(&g_cursor[d.x], 1);
        int p1 = atomicAdd(&g_cursor[d.y], 1);
        g_csr[p0] = s.x;
        g_csr[p1] = s.y;
    } else if (e < E) {
        int d = ei[E + e];
        int p = atomicAdd(&g_cursor[d], 1);
        g_csr[p] = ei[e];
    }
}

// ---------------------------------------------------------------------------
// Fused aggregate + softmax-normalize + bias + LayerNorm.
// One warp per destination node; lane l owns features [4l,4l+4).
// CSR indices fetched 32-at-a-time (one LDG per lane) and distributed via
// shuffles; 4-way unroll on the gather+FMA body for MLP.
// No segment-max needed (self-loops guarantee z>0; unshifted exp exact to
// fp32 tolerance at these logit scales).
// ---------------------------------------------------------------------------
__global__ void agg_kernel(const float* __restrict__ bias,
                           const float* __restrict__ gamma,
                           const float* __restrict__ beta,
                           float* __restrict__ out, int n) {
    const int wrp = (blockIdx.x * blockDim.x + threadIdx.x) >> 5;
    if (wrp >= n) return;
    const int lane = threadIdx.x & 31;
    const int h = lane >> 2;

    const int row = g_rowstart[wrp];
    const int deg = g_rowstart[wrp + 1] - row;
    const float adh = g_adst[(size_t)wrp * HH + h];
    const float4* __restrict__ xp4 = (const float4*)g_xp;

    float4 acc = make_float4(0.f, 0.f, 0.f, 0.f);
    float wsum = 0.f;

    for (int base = 0; base < deg; base += 32) {
        const int m = min(32, deg - base);
        int s_reg = (base + lane < deg) ? g_csr[row + base + lane] : 0;
        int j = 0;
        for (; j + 4 <= m; j += 4) {
            int s0 = __shfl_sync(0xffffffffu, s_reg, j + 0);
            int s1 = __shfl_sync(0xffffffffu, s_reg, j + 1);
            int s2 = __shfl_sync(0xffffffffu, s_reg, j + 2);
            int s3 = __shfl_sync(0xffffffffu, s_reg, j + 3);
            float a0 = g_asrc[(size_t)s0 * HH + h];
            float a1 = g_asrc[(size_t)s1 * HH + h];
            float a2 = g_asrc[(size_t)s2 * HH + h];
            float a3 = g_asrc[(size_t)s3 * HH + h];
            float4 x0 = xp4[(size_t)s0 * 32 + lane];
            float4 x1 = xp4[(size_t)s1 * 32 + lane];
            float4 x2 = xp4[(size_t)s2 * 32 + lane];
            float4 x3 = xp4[(size_t)s3 * 32 + lane];
            float v0 = a0 + adh; v0 = v0 > 0.f ? v0 : 0.2f * v0;
            float v1 = a1 + adh; v1 = v1 > 0.f ? v1 : 0.2f * v1;
            float v2 = a2 + adh; v2 = v2 > 0.f ? v2 : 0.2f * v2;
            float v3 = a3 + adh; v3 = v3 > 0.f ? v3 : 0.2f * v3;
            float w0 = __expf(v0), w1 = __expf(v1);
            float w2 = __expf(v2), w3 = __expf(v3);
            acc.x = fmaf(w0, x0.x, acc.x); acc.y = fmaf(w0, x0.y, acc.y);
            acc.z = fmaf(w0, x0.z, acc.z); acc.w = fmaf(w0, x0.w, acc.w);
            acc.x = fmaf(w1, x1.x, acc.x); acc.y = fmaf(w1, x1.y, acc.y);
            acc.z = fmaf(w1, x1.z, acc.z); acc.w = fmaf(w1, x1.w, acc.w);
            acc.x = fmaf(w2, x2.x, acc.x); acc.y = fmaf(w2, x2.y, acc.y);
            acc.z = fmaf(w2, x2.z, acc.z); acc.w = fmaf(w2, x2.w, acc.w);
            acc.x = fmaf(w3, x3.x, acc.x); acc.y = fmaf(w3, x3.y, acc.y);
            acc.z = fmaf(w3, x3.z, acc.z); acc.w = fmaf(w3, x3.w, acc.w);
            wsum += (w0 + w1) + (w2 + w3);
        }
        for (; j < m; j++) {
            int s = __shfl_sync(0xffffffffu, s_reg, j);
            float v = g_asrc[(size_t)s * HH + h] + adh;
            v = v > 0.f ? v : 0.2f * v;
            float wgt = __expf(v);
            float4 xv = xp4[(size_t)s * 32 + lane];
            acc.x = fmaf(wgt, xv.x, acc.x); acc.y = fmaf(wgt, xv.y, acc.y);
            acc.z = fmaf(wgt, xv.z, acc.z); acc.w = fmaf(wgt, xv.w, acc.w);
            wsum += wgt;
        }
    }

    // self loop
    {
        float v = g_asrc[(size_t)wrp * HH + h] + adh;
        v = v > 0.f ? v : 0.2f * v;
        float wgt = __expf(v);
        float4 xv = xp4[(size_t)wrp * 32 + lane];
        acc.x = fmaf(wgt, xv.x, acc.x); acc.y = fmaf(wgt, xv.y, acc.y);
        acc.z = fmaf(wgt, xv.z, acc.z); acc.w = fmaf(wgt, xv.w, acc.w);
        wsum += wgt;
    }

    const float inv_w = 1.f / wsum;
    float4 b4 = ((const float4*)bias)[lane];
    float4 o;
    o.x = acc.x * inv_w + b4.x;
    o.y = acc.y * inv_w + b4.y;
    o.z = acc.z * inv_w + b4.z;
    o.w = acc.w * inv_w + b4.w;

    float s1 = o.x + o.y + o.z + o.w;
    float s2 = o.x * o.x + o.y * o.y + o.z * o.z + o.w * o.w;
#pragma unroll
    for (int off = 16; off; off >>= 1) {
        s1 += __shfl_xor_sync(0xffffffffu, s1, off);
        s2 += __shfl_xor_sync(0xffffffffu, s2, off);
    }
    float mu  = s1 * (1.f / 128.f);
    float var = s2 * (1.f / 128.f) - mu * mu;
    float inv = rsqrtf(var + 1e-5f);

    float4 g4 = ((const float4*)gamma)[lane];
    float4 e4 = ((const float4*)beta)[lane];
    float4 r;
    r.x = (o.x - mu) * inv * g4.x + e4.x;
    r.y = (o.y - mu) * inv * g4.y + e4.y;
    r.z = (o.z - mu) * inv * g4.z + e4.z;
    r.w = (o.w - mu) * inv * g4.w + e4.w;
    ((float4*)out)[(size_t)wrp * 32 + lane] = r;
}

// ---------------------------------------------------------------------------
extern "C" void kernel_launch(void* const* d_in, const int* in_sizes, int n_in,
                              void* d_out, int out_size) {
    const float* x       = (const float*)d_in[0];
    const int*   ei      = (const int*)d_in[1];
    const float* W       = (const float*)d_in[2];
    const float* att_src = (const float*)d_in[3];
    const float* att_dst = (const float*)d_in[4];
    const float* bias    = (const float*)d_in[5];
    const float* gamma   = (const float*)d_in[6];
    const float* beta    = (const float*)d_in[7];
    float* out = (float*)d_out;

    const int n = in_sizes[0] / FD;   // 50000
    const int E = in_sizes[1] / 2;    // 800000

    zerocnt_kernel<<<(n + 1 + 255) / 256, 256>>>(n);              // 0
    hist_kernel<<<((E + 1) / 2 + 255) / 256, 256>>>(ei, E);       // 1
    scan_kernel<<<1, SB>>>(n);                                    // 2
    gemm_kernel<<<(n + 31) / 32, 128>>>(x, W, att_src, att_dst, n); // 3 (profiler slot)
    scatter_kernel<<<((E + 1) / 2 + 255) / 256, 256>>>(ei, E);    // 4
    agg_kernel<<<(n * 32 + 255) / 256, 256>>>(bias, gamma, beta, out, n); // 5
}

// round 6
// speedup vs baseline: 1.1935x; 1.1935x over previous
#include <cuda_runtime.h>
#include <cstdint>

#define NMAX 50048
#define EMAX 1000000
#define FD 128     // H*F_OUT == F_IN == 128
#define HH 8       // heads
#define SB 1024    // scan block size
#define GR 16      // gemm rows per block

// Scratch (static __device__ — no allocations allowed)
__device__ float g_xp[(size_t)NMAX * FD];      // x @ W            [N,128]
__device__ float g_asrc[(size_t)NMAX * HH];    // a_src            [N,8]
__device__ float g_adst[(size_t)NMAX * HH];    // a_dst            [N,8]
__device__ int   g_cnt[NMAX + 1];              // per-dst degree
__device__ int   g_rowstart[NMAX + 1];         // CSR row offsets
__device__ int   g_cursor[NMAX];               // scatter cursors
__device__ int   g_csr[EMAX];                  // src indices, grouped by dst

// ---------------------------------------------------------------------------
// xp = x @ W  (+ fused per-node attention logits a_src, a_dst)
// 16 rows per 128-thread block: ~44 regs -> ~46 warps/SM occupancy so the
// LDS/LDG latency in the FFMA chain is actually hidden (R5 ncu: 72 regs,
// occ 38%, fma 19.9% -> latency-bound, not FMA-floor-bound).
// ---------------------------------------------------------------------------
__global__ void gemm_kernel(const float* __restrict__ x,
                            const float* __restrict__ W,
                            const float* __restrict__ att_src,
                            const float* __restrict__ att_dst,
                            int n) {
    __shared__ float4 xs4[GR * 32];           // GR rows x 32 float4
    const int c  = threadIdx.x;               // output column 0..127
    const int r0 = blockIdx.x * GR;
    const int rows = min(GR, n - r0);

    const float4* x4 = (const float4*)x;
    for (int i = threadIdx.x; i < rows * 32; i += 128) {
        int r = i >> 5, k4 = i & 31;
        xs4[r * 32 + k4] = x4[(size_t)(r0 + r) * 32 + k4];
    }
    __syncthreads();

    float acc[GR];
#pragma unroll
    for (int r = 0; r < GR; r++) acc[r] = 0.f;

#pragma unroll 4
    for (int k4 = 0; k4 < 32; k4++) {
        float w0 = W[(k4 * 4 + 0) * FD + c];
        float w1 = W[(k4 * 4 + 1) * FD + c];
        float w2 = W[(k4 * 4 + 2) * FD + c];
        float w3 = W[(k4 * 4 + 3) * FD + c];
#pragma unroll
        for (int r = 0; r < GR; r++) {
            float4 xv = xs4[r * 32 + k4];     // broadcast LDS.128
            acc[r] = fmaf(xv.x, w0, acc[r]);
            acc[r] = fmaf(xv.y, w1, acc[r]);
            acc[r] = fmaf(xv.z, w2, acc[r]);
            acc[r] = fmaf(xv.w, w3, acc[r]);
        }
    }

    const float a_s = att_src[c];
    const float a_d = att_dst[c];
    const int lane = threadIdx.x & 31;
    for (int r = 0; r < rows; r++) {
        float v = acc[r];
        g_xp[(size_t)(r0 + r) * FD + c] = v;
        float vs = v * a_s, vd = v * a_d;
#pragma unroll
        for (int off = 8; off; off >>= 1) {
            vs += __shfl_xor_sync(0xffffffffu, vs, off, 16);
            vd += __shfl_xor_sync(0xffffffffu, vd, off, 16);
        }
        if ((lane & 15) == 0) {
            int h = c >> 4;
            g_asrc[(size_t)(r0 + r) * HH + h] = vs;
            g_adst[(size_t)(r0 + r) * HH + h] = vd;
        }
    }
}

// ---------------------------------------------------------------------------
// CSR build
// ---------------------------------------------------------------------------
__global__ void zerocnt_kernel(int n) {
    int i = blockIdx.x * blockDim.x + threadIdx.x;
    if (i <= n) g_cnt[i] = 0;
}

// 2 edges per thread
__global__ void hist_kernel(const int* __restrict__ ei, int E) {
    int t = blockIdx.x * blockDim.x + threadIdx.x;
    int e = t * 2;
    if (e + 1 < E) {
        int2 d = *(const int2*)&ei[E + e];
        atomicAdd(&g_cnt[d.x], 1);
        atomicAdd(&g_cnt[d.y], 1);
    } else if (e < E) {
        atomicAdd(&g_cnt[ei[E + e]], 1);
    }
}

// Single-block exclusive scan: g_cnt[0..n-1] -> g_rowstart[0..n] (+cursor)
__global__ void scan_kernel(int n) {
    const int t = threadIdx.x;
    const int per = (n + SB - 1) / SB;
    const int beg = min(t * per, n);
    const int fin = min(beg + per, n);

    int sum = 0;
    for (int i = beg; i < fin; i++) sum += g_cnt[i];

    const int lane = t & 31, wid = t >> 5;
    int xv = sum;
#pragma unroll
    for (int off = 1; off < 32; off <<= 1) {
        int y = __shfl_up_sync(0xffffffffu, xv, off);
        if (lane >= off) xv += y;
    }
    __shared__ int ws[32];
    if (lane == 31) ws[wid] = xv;
    __syncthreads();
    if (wid == 0) {
        int s = ws[lane];
#pragma unroll
        for (int off = 1; off < 32; off <<= 1) {
            int y = __shfl_up_sync(0xffffffffu, s, off);
            if (lane >= off) s += y;
        }
        ws[lane] = s;
    }
    __syncthreads();
    int run = xv - sum + (wid ? ws[wid - 1] : 0);   // exclusive offset

    for (int i = beg; i < fin; i++) {
        g_rowstart[i] = run;
        g_cursor[i]   = run;
        run += g_cnt[i];
    }
    if (t == 0) g_rowstart[n] = ws[31];             // grand total
}

// 2 edges per thread
__global__ void scatter_kernel(const int* __restrict__ ei, int E) {
    int t = blockIdx.x * blockDim.x + threadIdx.x;
    int e = t * 2;
    if (e + 1 < E) {
        int2 s = *(const int2*)&ei[e];
        int2 d = *(const int2*)&ei[E + e];
        int p0 = atomicAdd(&g_cursor[d.x], 1);
        int p1 = atomicAdd(&g_cursor[d.y], 1);
        g_csr[p0] = s.x;
        g_csr[p1] = s.y;
    } else if (e < E) {
        int d = ei[E + e];
        int p = atomicAdd(&g_cursor[d], 1);
        g_csr[p] = ei[e];
    }
}

// ---------------------------------------------------------------------------
// Fused aggregate + softmax-normalize + bias + LayerNorm (R4 version:
// direct sequential csr loads, 2-way unroll — the shuffle-distributed
// variant regressed badly in R5).
// One warp per destination node; lane l owns features [4l,4l+4).
// No segment-max needed (self-loops guarantee z>0; unshifted exp exact to
// fp32 tolerance at these logit scales).
// ---------------------------------------------------------------------------
__global__ void agg_kernel(const float* __restrict__ bias,
                           const float* __restrict__ gamma,
                           const float* __restrict__ beta,
                           float* __restrict__ out, int n) {
    const int wrp = (blockIdx.x * blockDim.x + threadIdx.x) >> 5;
    if (wrp >= n) return;
    const int lane = threadIdx.x & 31;
    const int h = lane >> 2;

    const int row = g_rowstart[wrp];
    const int end = g_rowstart[wrp + 1];
    const float adh = g_adst[(size_t)wrp * HH + h];
    const float4* __restrict__ xp4 = (const float4*)g_xp;

    float4 acc = make_float4(0.f, 0.f, 0.f, 0.f);
    float wsum = 0.f;

    int i = row;
    for (; i + 1 < end; i += 2) {
        int s0 = g_csr[i];
        int s1 = g_csr[i + 1];
        float a0 = g_asrc[(size_t)s0 * HH + h];
        float a1 = g_asrc[(size_t)s1 * HH + h];
        float4 x0 = xp4[(size_t)s0 * 32 + lane];
        float4 x1 = xp4[(size_t)s1 * 32 + lane];
        float v0 = a0 + adh; v0 = v0 > 0.f ? v0 : 0.2f * v0;
        float v1 = a1 + adh; v1 = v1 > 0.f ? v1 : 0.2f * v1;
        float w0 = __expf(v0);
        float w1 = __expf(v1);
        acc.x = fmaf(w0, x0.x, acc.x); acc.y = fmaf(w0, x0.y, acc.y);
        acc.z = fmaf(w0, x0.z, acc.z); acc.w = fmaf(w0, x0.w, acc.w);
        acc.x = fmaf(w1, x1.x, acc.x); acc.y = fmaf(w1, x1.y, acc.y);
        acc.z = fmaf(w1, x1.z, acc.z); acc.w = fmaf(w1, x1.w, acc.w);
        wsum += w0 + w1;
    }
    if (i < end) {
        int s = g_csr[i];
        float v = g_asrc[(size_t)s * HH + h] + adh;
        v = v > 0.f ? v : 0.2f * v;
        float wgt = __expf(v);
        float4 xv = xp4[(size_t)s * 32 + lane];
        acc.x = fmaf(wgt, xv.x, acc.x); acc.y = fmaf(wgt, xv.y, acc.y);
        acc.z = fmaf(wgt, xv.z, acc.z); acc.w = fmaf(wgt, xv.w, acc.w);
        wsum += wgt;
    }

    // self loop
    {
        float v = g_asrc[(size_t)wrp * HH + h] + adh;
        v = v > 0.f ? v : 0.2f * v;
        float wgt = __expf(v);
        float4 xv = xp4[(size_t)wrp * 32 + lane];
        acc.x = fmaf(wgt, xv.x, acc.x); acc.y = fmaf(wgt, xv.y, acc.y);
        acc.z = fmaf(wgt, xv.z, acc.z); acc.w = fmaf(wgt, xv.w, acc.w);
        wsum += wgt;
    }

    const float inv_w = 1.f / wsum;
    float4 b4 = ((const float4*)bias)[lane];
    float4 o;
    o.x = acc.x * inv_w + b4.x;
    o.y = acc.y * inv_w + b4.y;
    o.z = acc.z * inv_w + b4.z;
    o.w = acc.w * inv_w + b4.w;

    float s1 = o.x + o.y + o.z + o.w;
    float s2 = o.x * o.x + o.y * o.y + o.z * o.z + o.w * o.w;
#pragma unroll
    for (int off = 16; off; off >>= 1) {
        s1 += __shfl_xor_sync(0xffffffffu, s1, off);
        s2 += __shfl_xor_sync(0xffffffffu, s2, off);
    }
    float mu  = s1 * (1.f / 128.f);
    float var = s2 * (1.f / 128.f) - mu * mu;
    float inv = rsqrtf(var + 1e-5f);

    float4 g4 = ((const float4*)gamma)[lane];
    float4 e4 = ((const float4*)beta)[lane];
    float4 r;
    r.x = (o.x - mu) * inv * g4.x + e4.x;
    r.y = (o.y - mu) * inv * g4.y + e4.y;
    r.z = (o.z - mu) * inv * g4.z + e4.z;
    r.w = (o.w - mu) * inv * g4.w + e4.w;
    ((float4*)out)[(size_t)wrp * 32 + lane] = r;
}

// ---------------------------------------------------------------------------
extern "C" void kernel_launch(void* const* d_in, const int* in_sizes, int n_in,
                              void* d_out, int out_size) {
    const float* x       = (const float*)d_in[0];
    const int*   ei      = (const int*)d_in[1];
    const float* W       = (const float*)d_in[2];
    const float* att_src = (const float*)d_in[3];
    const float* att_dst = (const float*)d_in[4];
    const float* bias    = (const float*)d_in[5];
    const float* gamma   = (const float*)d_in[6];
    const float* beta    = (const float*)d_in[7];
    float* out = (float*)d_out;

    const int n = in_sizes[0] / FD;   // 50000
    const int E = in_sizes[1] / 2;    // 800000

    zerocnt_kernel<<<(n + 1 + 255) / 256, 256>>>(n);                 // 0
    hist_kernel<<<((E + 1) / 2 + 255) / 256, 256>>>(ei, E);          // 1
    scan_kernel<<<1, SB>>>(n);                                       // 2
    scatter_kernel<<<((E + 1) / 2 + 255) / 256, 256>>>(ei, E);       // 3
    gemm_kernel<<<(n + GR - 1) / GR, 128>>>(x, W, att_src, att_dst, n); // 4
    agg_kernel<<<(n * 32 + 255) / 256, 256>>>(bias, gamma, beta, out, n); // 5 (profiler slot)
}

// round 7
// speedup vs baseline: 1.2893x; 1.0803x over previous
#include <cuda_runtime.h>
#include <cstdint>

#define NMAX 50048
#define EMAX 1000000
#define FD 128     // H*F_OUT == F_IN == 128
#define HH 8       // heads
#define SB 1024    // scan block size
#define TM 64      // gemm tile rows
#define TN 64      // gemm tile cols
#define TP (TM + 4) // padded smem row length (keeps 16B align, kills conflicts)

// Scratch (static __device__ — no allocations allowed)
__device__ float g_xp[(size_t)NMAX * FD];      // x @ W            [N,128]
__device__ float g_asrc[(size_t)NMAX * HH];    // a_src            [N,8]
__device__ float g_adst[(size_t)NMAX * HH];    // a_dst            [N,8]
__device__ int   g_cnt[NMAX + 1];              // per-dst degree
__device__ int   g_rowstart[NMAX + 1];         // CSR row offsets
__device__ int   g_cursor[NMAX];               // scatter cursors
__device__ int   g_csr[EMAX];                  // src indices, grouped by dst

// ---------------------------------------------------------------------------
// Register-tiled SGEMM: xp = x @ W, 64x64 tile per 256-thread block,
// 4x4 micro-tile per thread (2 LDS.128 + 16 FFMA per k-step).
// Fused epilogue computes per-head attention logits a_src/a_dst.
// ---------------------------------------------------------------------------
__global__ __launch_bounds__(256) void gemm_kernel(
        const float* __restrict__ x,
        const float* __restrict__ W,
        const float* __restrict__ att_src,
        const float* __restrict__ att_dst,
        int n) {
    __shared__ float xT[FD * TP];             // [k][row] transposed x tile (~34KB)
    __shared__ float Ws[FD * TP];             // [k][col] W tile (~34KB, 64 cols used)

    const int tid  = threadIdx.x;
    const int tx   = tid & 15;                // col-quad index 0..15
    const int ty   = tid >> 4;                // row-quad index 0..15
    const int row0 = blockIdx.x * TM;
    const int colB = blockIdx.y;              // 0 or 1 -> cols [64*colB, 64*colB+64)

    // Load x tile transposed: xT[k][r] = x[row0+r][k].
    // idx: r fast within warp -> STS conflict-free (LDG pays 2x sectors, amortized).
    {
        const float4* x4 = (const float4*)x;
        for (int i = 0; i < 8; i++) {
            int idx = tid + 256 * i;          // 0..2047
            int r  = idx & 63;
            int k4 = idx >> 6;                // 0..31
            float4 v = make_float4(0.f, 0.f, 0.f, 0.f);
            if (row0 + r < n) v = x4[(size_t)(row0 + r) * 32 + k4];
            xT[(k4 * 4 + 0) * TP + r] = v.x;
            xT[(k4 * 4 + 1) * TP + r] = v.y;
            xT[(k4 * 4 + 2) * TP + r] = v.z;
            xT[(k4 * 4 + 3) * TP + r] = v.w;
        }
        // W tile: Ws[k][c] = W[k][colB*64 + c]
        for (int i = 0; i < 8; i++) {
            int idx = tid + 256 * i;          // 0..2047
            int c4 = idx & 15;
            int k  = idx >> 4;                // 0..127
            float4 v = *(const float4*)&W[(size_t)k * FD + colB * TN + c4 * 4];
            *(float4*)&Ws[k * TP + c4 * 4] = v;
        }
    }
    __syncthreads();

    float acc[4][4];
#pragma unroll
    for (int i = 0; i < 4; i++)
#pragma unroll
        for (int j = 0; j < 4; j++) acc[i][j] = 0.f;

#pragma unroll 4
    for (int k = 0; k < FD; k++) {
        float4 a = *(const float4*)&xT[k * TP + ty * 4];
        float4 b = *(const float4*)&Ws[k * TP + tx * 4];
        acc[0][0] = fmaf(a.x, b.x, acc[0][0]); acc[0][1] = fmaf(a.x, b.y, acc[0][1]);
        acc[0][2] = fmaf(a.x, b.z, acc[0][2]); acc[0][3] = fmaf(a.x, b.w, acc[0][3]);
        acc[1][0] = fmaf(a.y, b.x, acc[1][0]); acc[1][1] = fmaf(a.y, b.y, acc[1][1]);
        acc[1][2] = fmaf(a.y, b.z, acc[1][2]); acc[1][3] = fmaf(a.y, b.w, acc[1][3]);
        acc[2][0] = fmaf(a.z, b.x, acc[2][0]); acc[2][1] = fmaf(a.z, b.y, acc[2][1]);
        acc[2][2] = fmaf(a.z, b.z, acc[2][2]); acc[2][3] = fmaf(a.z, b.w, acc[2][3]);
        acc[3][0] = fmaf(a.w, b.x, acc[3][0]); acc[3][1] = fmaf(a.w, b.y, acc[3][1]);
        acc[3][2] = fmaf(a.w, b.z, acc[3][2]); acc[3][3] = fmaf(a.w, b.w, acc[3][3]);
    }

    // Epilogue: write xp tile + fused per-head logits.
    const int c0 = colB * TN + tx * 4;        // global col base (16B aligned)
    const int h  = c0 >> 4;                   // head owning cols c0..c0+3
    const float4 as4 = *(const float4*)&att_src[c0];
    const float4 ad4 = *(const float4*)&att_dst[c0];

#pragma unroll
    for (int i = 0; i < 4; i++) {
        int row = row0 + ty * 4 + i;
        bool ok = (row < n);
        float4 v = make_float4(acc[i][0], acc[i][1], acc[i][2], acc[i][3]);
        if (ok) *(float4*)&g_xp[(size_t)row * FD + c0] = v;

        float vs = v.x * as4.x + v.y * as4.y + v.z * as4.z + v.w * as4.w;
        float vd = v.x * ad4.x + v.y * ad4.y + v.z * ad4.z + v.w * ad4.w;
        // reduce across the 4 lanes (tx%4 group) covering this head's 16 cols
        vs += __shfl_xor_sync(0xffffffffu, vs, 1);
        vs += __shfl_xor_sync(0xffffffffu, vs, 2);
        vd += __shfl_xor_sync(0xffffffffu, vd, 1);
        vd += __shfl_xor_sync(0xffffffffu, vd, 2);
        if (ok && (tx & 3) == 0) {
            g_asrc[(size_t)row * HH + h] = vs;
            g_adst[(size_t)row * HH + h] = vd;
        }
    }
}

// ---------------------------------------------------------------------------
// CSR build
// ---------------------------------------------------------------------------
__global__ void zerocnt_kernel(int n) {
    int i = blockIdx.x * blockDim.x + threadIdx.x;
    if (i <= n) g_cnt[i] = 0;
}

// 2 edges per thread
__global__ void hist_kernel(const int* __restrict__ ei, int E) {
    int t = blockIdx.x * blockDim.x + threadIdx.x;
    int e = t * 2;
    if (e + 1 < E) {
        int2 d = *(const int2*)&ei[E + e];
        atomicAdd(&g_cnt[d.x], 1);
        atomicAdd(&g_cnt[d.y], 1);
    } else if (e < E) {
        atomicAdd(&g_cnt[ei[E + e]], 1);
    }
}

// Single-block exclusive scan: g_cnt[0..n-1] -> g_rowstart[0..n] (+cursor)
__global__ void scan_kernel(int n) {
    const int t = threadIdx.x;
    const int per = (n + SB - 1) / SB;
    const int beg = min(t * per, n);
    const int fin = min(beg + per, n);

    int sum = 0;
    for (int i = beg; i < fin; i++) sum += g_cnt[i];

    const int lane = t & 31, wid = t >> 5;
    int xv = sum;
#pragma unroll
    for (int off = 1; off < 32; off <<= 1) {
        int y = __shfl_up_sync(0xffffffffu, xv, off);
        if (lane >= off) xv += y;
    }
    __shared__ int ws[32];
    if (lane == 31) ws[wid] = xv;
    __syncthreads();
    if (wid == 0) {
        int s = ws[lane];
#pragma unroll
        for (int off = 1; off < 32; off <<= 1) {
            int y = __shfl_up_sync(0xffffffffu, s, off);
            if (lane >= off) s += y;
        }
        ws[lane] = s;
    }
    __syncthreads();
    int run = xv - sum + (wid ? ws[wid - 1] : 0);   // exclusive offset

    for (int i = beg; i < fin; i++) {
        g_rowstart[i] = run;
        g_cursor[i]   = run;
        run += g_cnt[i];
    }
    if (t == 0) g_rowstart[n] = ws[31];             // grand total
}

// 2 edges per thread
__global__ void scatter_kernel(const int* __restrict__ ei, int E) {
    int t = blockIdx.x * blockDim.x + threadIdx.x;
    int e = t * 2;
    if (e + 1 < E) {
        int2 s = *(const int2*)&ei[e];
        int2 d = *(const int2*)&ei[E + e];
        int p0 = atomicAdd(&g_cursor[d.x], 1);
        int p1 = atomicAdd(&g_cursor[d.y], 1);
        g_csr[p0] = s.x;
        g_csr[p1] = s.y;
    } else if (e < E) {
        int d = ei[E + e];
        int p = atomicAdd(&g_cursor[d], 1);
        g_csr[p] = ei[e];
    }
}

// ---------------------------------------------------------------------------
// Fused aggregate + softmax-normalize + bias + LayerNorm.
// One warp per destination node; lane l owns features [4l,4l+4).
// No segment-max needed (self-loops guarantee z>0; unshifted exp exact to
// fp32 tolerance at these logit scales).
// ---------------------------------------------------------------------------
__global__ void agg_kernel(const float* __restrict__ bias,
                           const float* __restrict__ gamma,
                           const float* __restrict__ beta,
                           float* __restrict__ out, int n) {
    const int wrp = (blockIdx.x * blockDim.x + threadIdx.x) >> 5;
    if (wrp >= n) return;
    const int lane = threadIdx.x & 31;
    const int h = lane >> 2;

    const int row = g_rowstart[wrp];
    const int end = g_rowstart[wrp + 1];
    const float adh = g_adst[(size_t)wrp * HH + h];
    const float4* __restrict__ xp4 = (const float4*)g_xp;

    float4 acc = make_float4(0.f, 0.f, 0.f, 0.f);
    float wsum = 0.f;

    int i = row;
    for (; i + 1 < end; i += 2) {
        int s0 = g_csr[i];
        int s1 = g_csr[i + 1];
        float a0 = g_asrc[(size_t)s0 * HH + h];
        float a1 = g_asrc[(size_t)s1 * HH + h];
        float4 x0 = xp4[(size_t)s0 * 32 + lane];
        float4 x1 = xp4[(size_t)s1 * 32 + lane];
        float v0 = a0 + adh; v0 = v0 > 0.f ? v0 : 0.2f * v0;
        float v1 = a1 + adh; v1 = v1 > 0.f ? v1 : 0.2f * v1;
        float w0 = __expf(v0);
        float w1 = __expf(v1);
        acc.x = fmaf(w0, x0.x, acc.x); acc.y = fmaf(w0, x0.y, acc.y);
        acc.z = fmaf(w0, x0.z, acc.z); acc.w = fmaf(w0, x0.w, acc.w);
        acc.x = fmaf(w1, x1.x, acc.x); acc.y = fmaf(w1, x1.y, acc.y);
        acc.z = fmaf(w1, x1.z, acc.z); acc.w = fmaf(w1, x1.w, acc.w);
        wsum += w0 + w1;
    }
    if (i < end) {
        int s = g_csr[i];
        float v = g_asrc[(size_t)s * HH + h] + adh;
        v = v > 0.f ? v : 0.2f * v;
        float wgt = __expf(v);
        float4 xv = xp4[(size_t)s * 32 + lane];
        acc.x = fmaf(wgt, xv.x, acc.x); acc.y = fmaf(wgt, xv.y, acc.y);
        acc.z = fmaf(wgt, xv.z, acc.z); acc.w = fmaf(wgt, xv.w, acc.w);
        wsum += wgt;
    }

    // self loop
    {
        float v = g_asrc[(size_t)wrp * HH + h] + adh;
        v = v > 0.f ? v : 0.2f * v;
        float wgt = __expf(v);
        float4 xv = xp4[(size_t)wrp * 32 + lane];
        acc.x = fmaf(wgt, xv.x, acc.x); acc.y = fmaf(wgt, xv.y, acc.y);
        acc.z = fmaf(wgt, xv.z, acc.z); acc.w = fmaf(wgt, xv.w, acc.w);
        wsum += wgt;
    }

    const float inv_w = 1.f / wsum;
    float4 b4 = ((const float4*)bias)[lane];
    float4 o;
    o.x = acc.x * inv_w + b4.x;
    o.y = acc.y * inv_w + b4.y;
    o.z = acc.z * inv_w + b4.z;
    o.w = acc.w * inv_w + b4.w;

    float s1 = o.x + o.y + o.z + o.w;
    float s2 = o.x * o.x + o.y * o.y + o.z * o.z + o.w * o.w;
#pragma unroll
    for (int off = 16; off; off >>= 1) {
        s1 += __shfl_xor_sync(0xffffffffu, s1, off);
        s2 += __shfl_xor_sync(0xffffffffu, s2, off);
    }
    float mu  = s1 * (1.f / 128.f);
    float var = s2 * (1.f / 128.f) - mu * mu;
    float inv = rsqrtf(var + 1e-5f);

    float4 g4 = ((const float4*)gamma)[lane];
    float4 e4 = ((const float4*)beta)[lane];
    float4 r;
    r.x = (o.x - mu) * inv * g4.x + e4.x;
    r.y = (o.y - mu) * inv * g4.y + e4.y;
    r.z = (o.z - mu) * inv * g4.z + e4.z;
    r.w = (o.w - mu) * inv * g4.w + e4.w;
    ((float4*)out)[(size_t)wrp * 32 + lane] = r;
}

// ---------------------------------------------------------------------------
extern "C" void kernel_launch(void* const* d_in, const int* in_sizes, int n_in,
                              void* d_out, int out_size) {
    const float* x       = (const float*)d_in[0];
    const int*   ei      = (const int*)d_in[1];
    const float* W       = (const float*)d_in[2];
    const float* att_src = (const float*)d_in[3];
    const float* att_dst = (const float*)d_in[4];
    const float* bias    = (const float*)d_in[5];
    const float* gamma   = (const float*)d_in[6];
    const float* beta    = (const float*)d_in[7];
    float* out = (float*)d_out;

    const int n = in_sizes[0] / FD;   // 50000
    const int E = in_sizes[1] / 2;    // 800000

    zerocnt_kernel<<<(n + 1 + 255) / 256, 256>>>(n);                 // 0
    hist_kernel<<<((E + 1) / 2 + 255) / 256, 256>>>(ei, E);          // 1
    scan_kernel<<<1, SB>>>(n);                                       // 2
    dim3 ggrid((n + TM - 1) / TM, FD / TN);
    gemm_kernel<<<ggrid, 256>>>(x, W, att_src, att_dst, n);          // 3 (profiler slot)
    scatter_kernel<<<((E + 1) / 2 + 255) / 256, 256>>>(ei, E);       // 4
    agg_kernel<<<(n * 32 + 255) / 256, 256>>>(bias, gamma, beta, out, n); // 5
}

// round 8
// speedup vs baseline: 2.0061x; 1.5560x over previous
#include <cuda_runtime.h>
#include <cstdint>

#define NMAX 50048
#define EMAX 1000000
#define FD 128     // H*F_OUT == F_IN == 128
#define HH 8       // heads
#define SB 1024    // scan block size
#define TM 64      // gemm tile rows
#define TN 64      // gemm tile cols
#define TP (TM + 4) // padded smem row length (keeps 16B align, kills conflicts)

// Scratch (static __device__ — no allocations allowed)
__device__ float g_xp[(size_t)NMAX * FD];      // x @ W            [N,128]
__device__ float g_asrc[(size_t)NMAX * HH];    // a_src            [N,8]
__device__ float g_adst[(size_t)NMAX * HH];    // a_dst            [N,8]
__device__ int   g_cnt[NMAX + 1];              // per-dst degree
__device__ int   g_rowstart[NMAX + 1];         // CSR row offsets
__device__ int   g_cursor[NMAX];               // scatter cursors
__device__ int   g_bsum[64];                   // scan block sums
__device__ int   g_csr[EMAX];                  // src indices, grouped by dst

// ---------------------------------------------------------------------------
// Register-tiled SGEMM: xp = x @ W, 64x64 tile per 256-thread block,
// 4x4 micro-tile per thread (2 LDS.128 + 16 FFMA per k-step).
// Fused epilogue computes per-head attention logits a_src/a_dst.
// ---------------------------------------------------------------------------
__global__ __launch_bounds__(256) void gemm_kernel(
        const float* __restrict__ x,
        const float* __restrict__ W,
        const float* __restrict__ att_src,
        const float* __restrict__ att_dst,
        int n) {
    __shared__ float xT[FD * TP];             // [k][row] transposed x tile
    __shared__ float Ws[FD * TP];             // [k][col] W tile (64 cols used)

    const int tid  = threadIdx.x;
    const int tx   = tid & 15;                // col-quad index 0..15
    const int ty   = tid >> 4;                // row-quad index 0..15
    const int row0 = blockIdx.x * TM;
    const int colB = blockIdx.y;              // 0 or 1 -> cols [64*colB, 64*colB+64)

    {
        const float4* x4 = (const float4*)x;
        for (int i = 0; i < 8; i++) {
            int idx = tid + 256 * i;          // 0..2047
            int r  = idx & 63;
            int k4 = idx >> 6;                // 0..31
            float4 v = make_float4(0.f, 0.f, 0.f, 0.f);
            if (row0 + r < n) v = x4[(size_t)(row0 + r) * 32 + k4];
            xT[(k4 * 4 + 0) * TP + r] = v.x;
            xT[(k4 * 4 + 1) * TP + r] = v.y;
            xT[(k4 * 4 + 2) * TP + r] = v.z;
            xT[(k4 * 4 + 3) * TP + r] = v.w;
        }
        for (int i = 0; i < 8; i++) {
            int idx = tid + 256 * i;          // 0..2047
            int c4 = idx & 15;
            int k  = idx >> 4;                // 0..127
            float4 v = *(const float4*)&W[(size_t)k * FD + colB * TN + c4 * 4];
            *(float4*)&Ws[k * TP + c4 * 4] = v;
        }
    }
    __syncthreads();

    float acc[4][4];
#pragma unroll
    for (int i = 0; i < 4; i++)
#pragma unroll
        for (int j = 0; j < 4; j++) acc[i][j] = 0.f;

#pragma unroll 4
    for (int k = 0; k < FD; k++) {
        float4 a = *(const float4*)&xT[k * TP + ty * 4];
        float4 b = *(const float4*)&Ws[k * TP + tx * 4];
        acc[0][0] = fmaf(a.x, b.x, acc[0][0]); acc[0][1] = fmaf(a.x, b.y, acc[0][1]);
        acc[0][2] = fmaf(a.x, b.z, acc[0][2]); acc[0][3] = fmaf(a.x, b.w, acc[0][3]);
        acc[1][0] = fmaf(a.y, b.x, acc[1][0]); acc[1][1] = fmaf(a.y, b.y, acc[1][1]);
        acc[1][2] = fmaf(a.y, b.z, acc[1][2]); acc[1][3] = fmaf(a.y, b.w, acc[1][3]);
        acc[2][0] = fmaf(a.z, b.x, acc[2][0]); acc[2][1] = fmaf(a.z, b.y, acc[2][1]);
        acc[2][2] = fmaf(a.z, b.z, acc[2][2]); acc[2][3] = fmaf(a.z, b.w, acc[2][3]);
        acc[3][0] = fmaf(a.w, b.x, acc[3][0]); acc[3][1] = fmaf(a.w, b.y, acc[3][1]);
        acc[3][2] = fmaf(a.w, b.z, acc[3][2]); acc[3][3] = fmaf(a.w, b.w, acc[3][3]);
    }

    // Epilogue: write xp tile + fused per-head logits.
    const int c0 = colB * TN + tx * 4;        // global col base (16B aligned)
    const int h  = c0 >> 4;                   // head owning cols c0..c0+3
    const float4 as4 = *(const float4*)&att_src[c0];
    const float4 ad4 = *(const float4*)&att_dst[c0];

#pragma unroll
    for (int i = 0; i < 4; i++) {
        int row = row0 + ty * 4 + i;
        bool ok = (row < n);
        float4 v = make_float4(acc[i][0], acc[i][1], acc[i][2], acc[i][3]);
        if (ok) *(float4*)&g_xp[(size_t)row * FD + c0] = v;

        float vs = v.x * as4.x + v.y * as4.y + v.z * as4.z + v.w * as4.w;
        float vd = v.x * ad4.x + v.y * ad4.y + v.z * ad4.z + v.w * ad4.w;
        vs += __shfl_xor_sync(0xffffffffu, vs, 1);
        vs += __shfl_xor_sync(0xffffffffu, vs, 2);
        vd += __shfl_xor_sync(0xffffffffu, vd, 1);
        vd += __shfl_xor_sync(0xffffffffu, vd, 2);
        if (ok && (tx & 3) == 0) {
            g_asrc[(size_t)row * HH + h] = vs;
            g_adst[(size_t)row * HH + h] = vd;
        }
    }
}

// ---------------------------------------------------------------------------
// CSR build: zero -> histogram -> scan trio (grid-wide) -> scatter
// ---------------------------------------------------------------------------
__global__ void zerocnt_kernel(int n) {
    int i = blockIdx.x * blockDim.x + threadIdx.x;
    if (i <= n) g_cnt[i] = 0;
}

// 2 edges per thread
__global__ void hist_kernel(const int* __restrict__ ei, int E) {
    int t = blockIdx.x * blockDim.x + threadIdx.x;
    int e = t * 2;
    if (e + 1 < E) {
        int2 d = *(const int2*)&ei[E + e];
        atomicAdd(&g_cnt[d.x], 1);
        atomicAdd(&g_cnt[d.y], 1);
    } else if (e < E) {
        atomicAdd(&g_cnt[ei[E + e]], 1);
    }
}

__global__ void scan1_kernel(int n) {
    const int i = blockIdx.x * SB + threadIdx.x;
    const int lane = threadIdx.x & 31, wid = threadIdx.x >> 5;
    int v = (i < n) ? g_cnt[i] : 0;
    int x = v;
#pragma unroll
    for (int off = 1; off < 32; off <<= 1) {
        int y = __shfl_up_sync(0xffffffffu, x, off);
        if (lane >= off) x += y;
    }
    __shared__ int ws[32];
    if (lane == 31) ws[wid] = x;
    __syncthreads();
    if (wid == 0) {
        int s = ws[lane];
#pragma unroll
        for (int off = 1; off < 32; off <<= 1) {
            int y = __shfl_up_sync(0xffffffffu, s, off);
            if (lane >= off) s += y;
        }
        ws[lane] = s;
    }
    __syncthreads();
    int excl = x - v + (wid ? ws[wid - 1] : 0);
    if (i <= n) g_rowstart[i] = excl;
    if (threadIdx.x == SB - 1) g_bsum[blockIdx.x] = excl + v;
}

// Parallel warp-shuffle exclusive scan over up to 64 block sums (1 warp).
__global__ void scan2_kernel(int nb) {
    const int lane = threadIdx.x;             // 32 threads
    int v0 = (lane < nb) ? g_bsum[lane] : 0;
    int v1 = (lane + 32 < nb) ? g_bsum[lane + 32] : 0;

    int x0 = v0;
#pragma unroll
    for (int off = 1; off < 32; off <<= 1) {
        int y = __shfl_up_sync(0xffffffffu, x0, off);
        if (lane >= off) x0 += y;
    }
    int tot0 = __shfl_sync(0xffffffffu, x0, 31);
    int x1 = v1;
#pragma unroll
    for (int off = 1; off < 32; off <<= 1) {
        int y = __shfl_up_sync(0xffffffffu, x1, off);
        if (lane >= off) x1 += y;
    }
    if (lane < nb)      g_bsum[lane]      = x0 - v0;
    if (lane + 32 < nb) g_bsum[lane + 32] = tot0 + x1 - v1;
}

__global__ void scan3_kernel(int n) {
    int i = blockIdx.x * SB + threadIdx.x;
    if (i <= n) {
        int v = g_rowstart[i] + g_bsum[blockIdx.x];
        g_rowstart[i] = v;
        if (i < n) g_cursor[i] = v;
    }
}

// 2 edges per thread
__global__ void scatter_kernel(const int* __restrict__ ei, int E) {
    int t = blockIdx.x * blockDim.x + threadIdx.x;
    int e = t * 2;
    if (e + 1 < E) {
        int2 s = *(const int2*)&ei[e];
        int2 d = *(const int2*)&ei[E + e];
        int p0 = atomicAdd(&g_cursor[d.x], 1);
        int p1 = atomicAdd(&g_cursor[d.y], 1);
        g_csr[p0] = s.x;
        g_csr[p1] = s.y;
    } else if (e < E) {
        int d = ei[E + e];
        int p = atomicAdd(&g_cursor[d], 1);
        g_csr[p] = ei[e];
    }
}

// ---------------------------------------------------------------------------
// Fused aggregate + softmax-normalize + bias + LayerNorm.
// One warp per destination node; lane l owns features [4l,4l+4).
// No segment-max needed (self-loops guarantee z>0; unshifted exp exact to
// fp32 tolerance at these logit scales).
// ---------------------------------------------------------------------------
__global__ void agg_kernel(const float* __restrict__ bias,
                           const float* __restrict__ gamma,
                           const float* __restrict__ beta,
                           float* __restrict__ out, int n) {
    const int wrp = (blockIdx.x * blockDim.x + threadIdx.x) >> 5;
    if (wrp >= n) return;
    const int lane = threadIdx.x & 31;
    const int h = lane >> 2;

    const int row = g_rowstart[wrp];
    const int end = g_rowstart[wrp + 1];
    const float adh = g_adst[(size_t)wrp * HH + h];
    const float4* __restrict__ xp4 = (const float4*)g_xp;

    float4 acc = make_float4(0.f, 0.f, 0.f, 0.f);
    float wsum = 0.f;

    int i = row;
    for (; i + 1 < end; i += 2) {
        int s0 = g_csr[i];
        int s1 = g_csr[i + 1];
        float a0 = g_asrc[(size_t)s0 * HH + h];
        float a1 = g_asrc[(size_t)s1 * HH + h];
        float4 x0 = xp4[(size_t)s0 * 32 + lane];
        float4 x1 = xp4[(size_t)s1 * 32 + lane];
        float v0 = a0 + adh; v0 = v0 > 0.f ? v0 : 0.2f * v0;
        float v1 = a1 + adh; v1 = v1 > 0.f ? v1 : 0.2f * v1;
        float w0 = __expf(v0);
        float w1 = __expf(v1);
        acc.x = fmaf(w0, x0.x, acc.x); acc.y = fmaf(w0, x0.y, acc.y);
        acc.z = fmaf(w0, x0.z, acc.z); acc.w = fmaf(w0, x0.w, acc.w);
        acc.x = fmaf(w1, x1.x, acc.x); acc.y = fmaf(w1, x1.y, acc.y);
        acc.z = fmaf(w1, x1.z, acc.z); acc.w = fmaf(w1, x1.w, acc.w);
        wsum += w0 + w1;
    }
    if (i < end) {
        int s = g_csr[i];
        float v = g_asrc[(size_t)s * HH + h] + adh;
        v = v > 0.f ? v : 0.2f * v;
        float wgt = __expf(v);
        float4 xv = xp4[(size_t)s * 32 + lane];
        acc.x = fmaf(wgt, xv.x, acc.x); acc.y = fmaf(wgt, xv.y, acc.y);
        acc.z = fmaf(wgt, xv.z, acc.z); acc.w = fmaf(wgt, xv.w, acc.w);
        wsum += wgt;
    }

    // self loop
    {
        float v = g_asrc[(size_t)wrp * HH + h] + adh;
        v = v > 0.f ? v : 0.2f * v;
        float wgt = __expf(v);
        float4 xv = xp4[(size_t)wrp * 32 + lane];
        acc.x = fmaf(wgt, xv.x, acc.x); acc.y = fmaf(wgt, xv.y, acc.y);
        acc.z = fmaf(wgt, xv.z, acc.z); acc.w = fmaf(wgt, xv.w, acc.w);
        wsum += wgt;
    }

    const float inv_w = 1.f / wsum;
    float4 b4 = ((const float4*)bias)[lane];
    float4 o;
    o.x = acc.x * inv_w + b4.x;
    o.y = acc.y * inv_w + b4.y;
    o.z = acc.z * inv_w + b4.z;
    o.w = acc.w * inv_w + b4.w;

    float s1 = o.x + o.y + o.z + o.w;
    float s2 = o.x * o.x + o.y * o.y + o.z * o.z + o.w * o.w;
#pragma unroll
    for (int off = 16; off; off >>= 1) {
        s1 += __shfl_xor_sync(0xffffffffu, s1, off);
        s2 += __shfl_xor_sync(0xffffffffu, s2, off);
    }
    float mu  = s1 * (1.f / 128.f);
    float var = s2 * (1.f / 128.f) - mu * mu;
    float inv = rsqrtf(var + 1e-5f);

    float4 g4 = ((const float4*)gamma)[lane];
    float4 e4 = ((const float4*)beta)[lane];
    float4 r;
    r.x = (o.x - mu) * inv * g4.x + e4.x;
    r.y = (o.y - mu) * inv * g4.y + e4.y;
    r.z = (o.z - mu) * inv * g4.z + e4.z;
    r.w = (o.w - mu) * inv * g4.w + e4.w;
    ((float4*)out)[(size_t)wrp * 32 + lane] = r;
}

// ---------------------------------------------------------------------------
extern "C" void kernel_launch(void* const* d_in, const int* in_sizes, int n_in,
                              void* d_out, int out_size) {
    const float* x       = (const float*)d_in[0];
    const int*   ei      = (const int*)d_in[1];
    const float* W       = (const float*)d_in[2];
    const float* att_src = (const float*)d_in[3];
    const float* att_dst = (const float*)d_in[4];
    const float* bias    = (const float*)d_in[5];
    const float* gamma   = (const float*)d_in[6];
    const float* beta    = (const float*)d_in[7];
    float* out = (float*)d_out;

    const int n = in_sizes[0] / FD;   // 50000
    const int E = in_sizes[1] / 2;    // 800000
    const int nb = (n + 1 + SB - 1) / SB;

    zerocnt_kernel<<<(n + 1 + 255) / 256, 256>>>(n);                 // 0
    hist_kernel<<<((E + 1) / 2 + 255) / 256, 256>>>(ei, E);          // 1
    scan1_kernel<<<nb, SB>>>(n);                                     // 2
    dim3 ggrid((n + TM - 1) / TM, FD / TN);
    gemm_kernel<<<ggrid, 256>>>(x, W, att_src, att_dst, n);          // 3 (profiler slot)
    scan2_kernel<<<1, 32>>>(nb);                                     // 4
    scan3_kernel<<<nb, SB>>>(n);                                     // 5
    scatter_kernel<<<((E + 1) / 2 + 255) / 256, 256>>>(ei, E);       // 6
    agg_kernel<<<(n * 32 + 255) / 256, 256>>>(bias, gamma, beta, out, n); // 7
}

// round 9
// speedup vs baseline: 2.0791x; 1.0364x over previous
#include <cuda_runtime.h>
#include <cstdint>

#define NMAX 50048
#define EMAX 1000000
#define FD 128     // H*F_OUT == F_IN == 128
#define HH 8       // heads
#define SB 1024    // scan block size
#define TM 128     // gemm tile rows
#define TN 128     // gemm tile cols

// Scratch (static __device__ — no allocations allowed)
__device__ float g_xp[(size_t)NMAX * FD];      // x @ W            [N,128]
__device__ float g_asrc[(size_t)NMAX * HH];    // a_src            [N,8]
__device__ float g_adst[(size_t)NMAX * HH];    // a_dst            [N,8]
__device__ int   g_cnt[NMAX + 1];              // per-dst degree
__device__ int   g_rowstart[NMAX + 1];         // CSR row offsets
__device__ int   g_cursor[NMAX];               // scatter cursors
__device__ int   g_bsum[64];                   // scan block sums
__device__ int   g_csr[EMAX];                  // src indices, grouped by dst

// ---------------------------------------------------------------------------
// Register-tiled SGEMM: xp = x @ W, 128x128 tile per 256-thread block,
// 8x8 micro-tile per thread (4 LDS.128 per 64 FFMA -> 1 B/FFMA, halving the
// L1 wavefront traffic that bound the 4x4 version at 77.5% L1).
// Fused epilogue computes per-head attention logits a_src/a_dst.
// ---------------------------------------------------------------------------
__global__ __launch_bounds__(256) void gemm_kernel(
        const float* __restrict__ x,
        const float* __restrict__ W,
        const float* __restrict__ att_src,
        const float* __restrict__ att_dst,
        int n) {
    __shared__ float xT[FD * TM];             // [k][row] transposed x tile (64KB)
    __shared__ float Ws[FD * TN];             // [k][col] W tile (64KB)

    const int tid  = threadIdx.x;
    const int tx   = tid & 15;                // col-octet index 0..15
    const int ty   = tid >> 4;                // row-octet index 0..15
    const int row0 = blockIdx.x * TM;

    // Fill x tile transposed: xT[k][r] = x[row0+r][k]
    {
        const float4* x4 = (const float4*)x;
#pragma unroll
        for (int i = 0; i < 16; i++) {
            int idx = tid + 256 * i;          // 0..4095
            int r  = idx & 127;
            int k4 = idx >> 7;                // 0..31
            float4 v = make_float4(0.f, 0.f, 0.f, 0.f);
            if (row0 + r < n) v = x4[(size_t)(row0 + r) * 32 + k4];
            xT[(k4 * 4 + 0) * TM + r] = v.x;
            xT[(k4 * 4 + 1) * TM + r] = v.y;
            xT[(k4 * 4 + 2) * TM + r] = v.z;
            xT[(k4 * 4 + 3) * TM + r] = v.w;
        }
        // Full-width W tile: Ws[k][c] = W[k][c]
#pragma unroll
        for (int i = 0; i < 16; i++) {
            int idx = tid + 256 * i;          // 0..4095
            int c4 = idx & 31;
            int k  = idx >> 5;                // 0..127
            *(float4*)&Ws[k * TN + c4 * 4] =
                *(const float4*)&W[(size_t)k * FD + c4 * 4];
        }
    }
    __syncthreads();

    float acc[8][8];
#pragma unroll
    for (int i = 0; i < 8; i++)
#pragma unroll
        for (int j = 0; j < 8; j++) acc[i][j] = 0.f;

#pragma unroll 2
    for (int k = 0; k < FD; k++) {
        float a[8], b[8];
        *(float4*)&a[0] = *(const float4*)&xT[k * TM + ty * 8];
        *(float4*)&a[4] = *(const float4*)&xT[k * TM + ty * 8 + 4];
        *(float4*)&b[0] = *(const float4*)&Ws[k * TN + tx * 8];
        *(float4*)&b[4] = *(const float4*)&Ws[k * TN + tx * 8 + 4];
#pragma unroll
        for (int i = 0; i < 8; i++)
#pragma unroll
            for (int j = 0; j < 8; j++)
                acc[i][j] = fmaf(a[i], b[j], acc[i][j]);
    }

    // Epilogue: write xp tile + fused per-head logits.
    // Each thread's 8 cols [tx*8, tx*8+8) lie inside head h = tx>>1;
    // the xor-1 lane partner covers the other 8 cols of the head.
    const int c0 = tx * 8;
    const int h  = tx >> 1;
    float as8[8], ad8[8];
    *(float4*)&as8[0] = *(const float4*)&att_src[c0];
    *(float4*)&as8[4] = *(const float4*)&att_src[c0 + 4];
    *(float4*)&ad8[0] = *(const float4*)&att_dst[c0];
    *(float4*)&ad8[4] = *(const float4*)&att_dst[c0 + 4];

#pragma unroll
    for (int i = 0; i < 8; i++) {
        int row = row0 + ty * 8 + i;
        bool ok = (row < n);
        if (ok) {
            *(float4*)&g_xp[(size_t)row * FD + c0]     =
                make_float4(acc[i][0], acc[i][1], acc[i][2], acc[i][3]);
            *(float4*)&g_xp[(size_t)row * FD + c0 + 4] =
                make_float4(acc[i][4], acc[i][5], acc[i][6], acc[i][7]);
        }
        float vs = 0.f, vd = 0.f;
#pragma unroll
        for (int j = 0; j < 8; j++) {
            vs = fmaf(acc[i][j], as8[j], vs);
            vd = fmaf(acc[i][j], ad8[j], vd);
        }
        vs += __shfl_xor_sync(0xffffffffu, vs, 1);
        vd += __shfl_xor_sync(0xffffffffu, vd, 1);
        if (ok && (tx & 1) == 0) {
            g_asrc[(size_t)row * HH + h] = vs;
            g_adst[(size_t)row * HH + h] = vd;
        }
    }
}

// ---------------------------------------------------------------------------
// CSR build: zero -> histogram -> scan trio (grid-wide) -> scatter
// ---------------------------------------------------------------------------
__global__ void zerocnt_kernel(int n) {
    int i = blockIdx.x * blockDim.x + threadIdx.x;
    if (i <= n) g_cnt[i] = 0;
}

// 2 edges per thread
__global__ void hist_kernel(const int* __restrict__ ei, int E) {
    int t = blockIdx.x * blockDim.x + threadIdx.x;
    int e = t * 2;
    if (e + 1 < E) {
        int2 d = *(const int2*)&ei[E + e];
        atomicAdd(&g_cnt[d.x], 1);
        atomicAdd(&g_cnt[d.y], 1);
    } else if (e < E) {
        atomicAdd(&g_cnt[ei[E + e]], 1);
    }
}

__global__ void scan1_kernel(int n) {
    const int i = blockIdx.x * SB + threadIdx.x;
    const int lane = threadIdx.x & 31, wid = threadIdx.x >> 5;
    int v = (i < n) ? g_cnt[i] : 0;
    int x = v;
#pragma unroll
    for (int off = 1; off < 32; off <<= 1) {
        int y = __shfl_up_sync(0xffffffffu, x, off);
        if (lane >= off) x += y;
    }
    __shared__ int ws[32];
    if (lane == 31) ws[wid] = x;
    __syncthreads();
    if (wid == 0) {
        int s = ws[lane];
#pragma unroll
        for (int off = 1; off < 32; off <<= 1) {
            int y = __shfl_up_sync(0xffffffffu, s, off);
            if (lane >= off) s += y;
        }
        ws[lane] = s;
    }
    __syncthreads();
    int excl = x - v + (wid ? ws[wid - 1] : 0);
    if (i <= n) g_rowstart[i] = excl;
    if (threadIdx.x == SB - 1) g_bsum[blockIdx.x] = excl + v;
}

// Parallel warp-shuffle exclusive scan over up to 64 block sums (1 warp).
__global__ void scan2_kernel(int nb) {
    const int lane = threadIdx.x;             // 32 threads
    int v0 = (lane < nb) ? g_bsum[lane] : 0;
    int v1 = (lane + 32 < nb) ? g_bsum[lane + 32] : 0;

    int x0 = v0;
#pragma unroll
    for (int off = 1; off < 32; off <<= 1) {
        int y = __shfl_up_sync(0xffffffffu, x0, off);
        if (lane >= off) x0 += y;
    }
    int tot0 = __shfl_sync(0xffffffffu, x0, 31);
    int x1 = v1;
#pragma unroll
    for (int off = 1; off < 32; off <<= 1) {
        int y = __shfl_up_sync(0xffffffffu, x1, off);
        if (lane >= off) x1 += y;
    }
    if (lane < nb)      g_bsum[lane]      = x0 - v0;
    if (lane + 32 < nb) g_bsum[lane + 32] = tot0 + x1 - v1;
}

__global__ void scan3_kernel(int n) {
    int i = blockIdx.x * SB + threadIdx.x;
    if (i <= n) {
        int v = g_rowstart[i] + g_bsum[blockIdx.x];
        g_rowstart[i] = v;
        if (i < n) g_cursor[i] = v;
    }
}

// 2 edges per thread
__global__ void scatter_kernel(const int* __restrict__ ei, int E) {
    int t = blockIdx.x * blockDim.x + threadIdx.x;
    int e = t * 2;
    if (e + 1 < E) {
        int2 s = *(const int2*)&ei[e];
        int2 d = *(const int2*)&ei[E + e];
        int p0 = atomicAdd(&g_cursor[d.x], 1);
        int p1 = atomicAdd(&g_cursor[d.y], 1);
        g_csr[p0] = s.x;
        g_csr[p1] = s.y;
    } else if (e < E) {
        int d = ei[E + e];
        int p = atomicAdd(&g_cursor[d], 1);
        g_csr[p] = ei[e];
    }
}

// ---------------------------------------------------------------------------
// Fused aggregate + softmax-normalize + bias + LayerNorm.
// One warp per destination node; lane l owns features [4l,4l+4).
// No segment-max needed (self-loops guarantee z>0; unshifted exp exact to
// fp32 tolerance at these logit scales).
// ---------------------------------------------------------------------------
__global__ void agg_kernel(const float* __restrict__ bias,
                           const float* __restrict__ gamma,
                           const float* __restrict__ beta,
                           float* __restrict__ out, int n) {
    const int wrp = (blockIdx.x * blockDim.x + threadIdx.x) >> 5;
    if (wrp >= n) return;
    const int lane = threadIdx.x & 31;
    const int h = lane >> 2;

    const int row = g_rowstart[wrp];
    const int end = g_rowstart[wrp + 1];
    const float adh = g_adst[(size_t)wrp * HH + h];
    const float4* __restrict__ xp4 = (const float4*)g_xp;

    float4 acc = make_float4(0.f, 0.f, 0.f, 0.f);
    float wsum = 0.f;

    int i = row;
    for (; i + 1 < end; i += 2) {
        int s0 = g_csr[i];
        int s1 = g_csr[i + 1];
        float a0 = g_asrc[(size_t)s0 * HH + h];
        float a1 = g_asrc[(size_t)s1 * HH + h];
        float4 x0 = xp4[(size_t)s0 * 32 + lane];
        float4 x1 = xp4[(size_t)s1 * 32 + lane];
        float v0 = a0 + adh; v0 = v0 > 0.f ? v0 : 0.2f * v0;
        float v1 = a1 + adh; v1 = v1 > 0.f ? v1 : 0.2f * v1;
        float w0 = __expf(v0);
        float w1 = __expf(v1);
        acc.x = fmaf(w0, x0.x, acc.x); acc.y = fmaf(w0, x0.y, acc.y);
        acc.z = fmaf(w0, x0.z, acc.z); acc.w = fmaf(w0, x0.w, acc.w);
        acc.x = fmaf(w1, x1.x, acc.x); acc.y = fmaf(w1, x1.y, acc.y);
        acc.z = fmaf(w1, x1.z, acc.z); acc.w = fmaf(w1, x1.w, acc.w);
        wsum += w0 + w1;
    }
    if (i < end) {
        int s = g_csr[i];
        float v = g_asrc[(size_t)s * HH + h] + adh;
        v = v > 0.f ? v : 0.2f * v;
        float wgt = __expf(v);
        float4 xv = xp4[(size_t)s * 32 + lane];
        acc.x = fmaf(wgt, xv.x, acc.x); acc.y = fmaf(wgt, xv.y, acc.y);
        acc.z = fmaf(wgt, xv.z, acc.z); acc.w = fmaf(wgt, xv.w, acc.w);
        wsum += wgt;
    }

    // self loop
    {
        float v = g_asrc[(size_t)wrp * HH + h] + adh;
        v = v > 0.f ? v : 0.2f * v;
        float wgt = __expf(v);
        float4 xv = xp4[(size_t)wrp * 32 + lane];
        acc.x = fmaf(wgt, xv.x, acc.x); acc.y = fmaf(wgt, xv.y, acc.y);
        acc.z = fmaf(wgt, xv.z, acc.z); acc.w = fmaf(wgt, xv.w, acc.w);
        wsum += wgt;
    }

    const float inv_w = 1.f / wsum;
    float4 b4 = ((const float4*)bias)[lane];
    float4 o;
    o.x = acc.x * inv_w + b4.x;
    o.y = acc.y * inv_w + b4.y;
    o.z = acc.z * inv_w + b4.z;
    o.w = acc.w * inv_w + b4.w;

    float s1 = o.x + o.y + o.z + o.w;
    float s2 = o.x * o.x + o.y * o.y + o.z * o.z + o.w * o.w;
#pragma unroll
    for (int off = 16; off; off >>= 1) {
        s1 += __shfl_xor_sync(0xffffffffu, s1, off);
        s2 += __shfl_xor_sync(0xffffffffu, s2, off);
    }
    float mu  = s1 * (1.f / 128.f);
    float var = s2 * (1.f / 128.f) - mu * mu;
    float inv = rsqrtf(var + 1e-5f);

    float4 g4 = ((const float4*)gamma)[lane];
    float4 e4 = ((const float4*)beta)[lane];
    float4 r;
    r.x = (o.x - mu) * inv * g4.x + e4.x;
    r.y = (o.y - mu) * inv * g4.y + e4.y;
    r.z = (o.z - mu) * inv * g4.z + e4.z;
    r.w = (o.w - mu) * inv * g4.w + e4.w;
    ((float4*)out)[(size_t)wrp * 32 + lane] = r;
}

// ---------------------------------------------------------------------------
extern "C" void kernel_launch(void* const* d_in, const int* in_sizes, int n_in,
                              void* d_out, int out_size) {
    const float* x       = (const float*)d_in[0];
    const int*   ei      = (const int*)d_in[1];
    const float* W       = (const float*)d_in[2];
    const float* att_src = (const float*)d_in[3];
    const float* att_dst = (const float*)d_in[4];
    const float* bias    = (const float*)d_in[5];
    const float* gamma   = (const float*)d_in[6];
    const float* beta    = (const float*)d_in[7];
    float* out = (float*)d_out;

    const int n = in_sizes[0] / FD;   // 50000
    const int E = in_sizes[1] / 2;    // 800000
    const int nb = (n + 1 + SB - 1) / SB;

    zerocnt_kernel<<<(n + 1 + 255) / 256, 256>>>(n);                 // 0
    hist_kernel<<<((E + 1) / 2 + 255) / 256, 256>>>(ei, E);          // 1
    scan1_kernel<<<nb, SB>>>(n);                                     // 2
    gemm_kernel<<<(n + TM - 1) / TM, 256>>>(x, W, att_src, att_dst, n); // 3 (profiler slot)
    scan2_kernel<<<1, 32>>>(nb);                                     // 4
    scan3_kernel<<<nb, SB>>>(n);                                     // 5
    scatter_kernel<<<((E + 1) / 2 + 255) / 256, 256>>>(ei, E);       // 6
    agg_kernel<<<(n * 32 + 255) / 256, 256>>>(bias, gamma, beta, out, n); // 7
}

// round 11
// speedup vs baseline: 2.5656x; 1.2340x over previous
#include <cuda_runtime.h>
#include <cuda_bf16.h>
#include <cstdint>

#define NMAX 50048
#define EMAX 1000000
#define FD 128     // H*F_OUT == F_IN == 128
#define HH 8       // heads
#define SB 1024    // scan block size
#define TMR 128    // gemm rows per block
#define SXP 132    // padded sX row stride (floats)

// Scratch (static __device__ — no allocations allowed)
__device__ float g_xp[(size_t)NMAX * FD];
__device__ float g_asrc[(size_t)NMAX * HH];
__device__ float g_adst[(size_t)NMAX * HH];
__device__ int   g_cnt[NMAX + 1];
__device__ int   g_rowstart[NMAX + 1];
__device__ int   g_cursor[NMAX];
__device__ int   g_bsum[64];
__device__ int   g_csr[EMAX];
// Pre-packed W fragments for mma.m16n8k16 (kc 0..7, nt 0..15, lane 0..31)
__device__ uint2 g_wbhi[8 * 16 * 32];
__device__ uint2 g_wblo[8 * 16 * 32];

__device__ __forceinline__ void mma16816(float* c, const unsigned* a, uint2 b) {
    asm volatile("mma.sync.aligned.m16n8k16.row.col.f32.bf16.bf16.f32 "
                 "{%0,%1,%2,%3}, {%4,%5,%6,%7}, {%8,%9}, {%0,%1,%2,%3};"
                 : "+f"(c[0]), "+f"(c[1]), "+f"(c[2]), "+f"(c[3])
                 : "r"(a[0]), "r"(a[1]), "r"(a[2]), "r"(a[3]),
                   "r"(b.x), "r"(b.y));
}
__device__ __forceinline__ unsigned bf2_hi(float x, float y, float2& back) {
    __nv_bfloat162 h = __floats2bfloat162_rn(x, y);
    back = __bfloat1622float2(h);
    return *(unsigned*)&h;
}
__device__ __forceinline__ unsigned bf2_pack(float x, float y) {
    __nv_bfloat162 h = __floats2bfloat162_rn(x, y);
    return *(unsigned*)&h;
}

// ---------------------------------------------------------------------------
// Prep: pack W into per-lane mma fragments, split bf16 hi + residual lo.
// b0 = W[k0..k0+1][n], b1 = W[k0+8..k0+9][n]; n = nt*8+g, k0 = kc*16+2t.
// ---------------------------------------------------------------------------
__global__ void wfrag_prep(const float* __restrict__ W) {
    int idx = blockIdx.x * blockDim.x + threadIdx.x;   // 0..4095
    if (idx >= 8 * 16 * 32) return;
    int lane = idx & 31;
    int nt   = (idx >> 5) & 15;
    int kc   = idx >> 9;
    int g = lane >> 2, t = lane & 3;
    int nn = nt * 8 + g;
    int k0 = kc * 16 + t * 2;
    float w00 = W[(size_t)k0 * FD + nn];
    float w01 = W[(size_t)(k0 + 1) * FD + nn];
    float w10 = W[(size_t)(k0 + 8) * FD + nn];
    float w11 = W[(size_t)(k0 + 9) * FD + nn];
    float2 f0, f1;
    unsigned h0 = bf2_hi(w00, w01, f0);
    unsigned h1 = bf2_hi(w10, w11, f1);
    g_wbhi[idx] = make_uint2(h0, h1);
    g_wblo[idx] = make_uint2(bf2_pack(w00 - f0.x, w01 - f0.y),
                             bf2_pack(w10 - f1.x, w11 - f1.y));
}

// ---------------------------------------------------------------------------
// Tensor-core GEMM via baseline mma.sync bf16 split precision:
// xp = x @ W  computed as hi@Whi + hi@Wlo + lo@Whi  (fp32 accumulate).
// 256 threads / 128 rows per block; warp w owns rows [16w,16w+16).
// Fused epilogue writes xp + per-head attention logits.
// ---------------------------------------------------------------------------
__global__ __launch_bounds__(256) void gemm_mma(
        const float* __restrict__ x,
        const float* __restrict__ att_src,
        const float* __restrict__ att_dst,
        int n) {
    __shared__ float sX[TMR * SXP];
    __shared__ float s_att[256];

    const int tid  = threadIdx.x;
    const int w    = tid >> 5;
    const int lane = tid & 31;
    const int g = lane >> 2, t = lane & 3;
    const int row0 = blockIdx.x * TMR;

    {
        const float4* x4 = (const float4*)x;
#pragma unroll
        for (int i = 0; i < 16; i++) {
            int idx = tid + 256 * i;              // 0..4095
            int r  = idx >> 5;
            int c4 = idx & 31;
            float4 v = make_float4(0.f, 0.f, 0.f, 0.f);
            if (row0 + r < n) v = x4[(size_t)(row0 + r) * 32 + c4];
            *(float4*)&sX[r * SXP + c4 * 4] = v;
        }
        s_att[tid] = (tid < 128) ? att_src[tid] : att_dst[tid - 128];
    }
    __syncthreads();

    float acc[16][4];
#pragma unroll
    for (int nt = 0; nt < 16; nt++)
#pragma unroll
        for (int j = 0; j < 4; j++) acc[nt][j] = 0.f;

    const int wr = w * 16;
#pragma unroll
    for (int kc = 0; kc < 8; kc++) {
        const int cb = kc * 16 + t * 2;
        float2 p00 = *(const float2*)&sX[(wr + g)     * SXP + cb];
        float2 p10 = *(const float2*)&sX[(wr + g + 8) * SXP + cb];
        float2 p01 = *(const float2*)&sX[(wr + g)     * SXP + cb + 8];
        float2 p11 = *(const float2*)&sX[(wr + g + 8) * SXP + cb + 8];

        float2 f00, f10, f01, f11;
        unsigned ahi[4], alo[4];
        ahi[0] = bf2_hi(p00.x, p00.y, f00);
        ahi[1] = bf2_hi(p10.x, p10.y, f10);
        ahi[2] = bf2_hi(p01.x, p01.y, f01);
        ahi[3] = bf2_hi(p11.x, p11.y, f11);
        alo[0] = bf2_pack(p00.x - f00.x, p00.y - f00.y);
        alo[1] = bf2_pack(p10.x - f10.x, p10.y - f10.y);
        alo[2] = bf2_pack(p01.x - f01.x, p01.y - f01.y);
        alo[3] = bf2_pack(p11.x - f11.x, p11.y - f11.y);

        const uint2* __restrict__ bh = &g_wbhi[kc * 512 + lane];
        const uint2* __restrict__ bl = &g_wblo[kc * 512 + lane];
#pragma unroll
        for (int nt = 0; nt < 16; nt++) {
            uint2 bhv = bh[nt * 32];
            uint2 blv = bl[nt * 32];
            mma16816(acc[nt], ahi, bhv);
            mma16816(acc[nt], alo, bhv);
            mma16816(acc[nt], ahi, blv);
        }
    }

    // Epilogue: rows r0 = row0+wr+g, r1 = r0+8; lane holds cols nt*8+2t, +1.
    const int r0 = row0 + wr + g;
    const int r1 = r0 + 8;
    const bool ok0 = r0 < n, ok1 = r1 < n;

    float vs0[8], vd0[8], vs1[8], vd1[8];
#pragma unroll
    for (int i = 0; i < 8; i++) { vs0[i] = vd0[i] = vs1[i] = vd1[i] = 0.f; }

#pragma unroll
    for (int nt = 0; nt < 16; nt++) {
        int c = nt * 8 + t * 2;
        int h = nt >> 1;
        if (ok0) *(float2*)&g_xp[(size_t)r0 * FD + c] = make_float2(acc[nt][0], acc[nt][1]);
        if (ok1) *(float2*)&g_xp[(size_t)r1 * FD + c] = make_float2(acc[nt][2], acc[nt][3]);
        float as0 = s_att[c], as1 = s_att[c + 1];
        float ad0 = s_att[128 + c], ad1 = s_att[128 + c + 1];
        vs0[h] += acc[nt][0] * as0 + acc[nt][1] * as1;
        vd0[h] += acc[nt][0] * ad0 + acc[nt][1] * ad1;
        vs1[h] += acc[nt][2] * as0 + acc[nt][3] * as1;
        vd1[h] += acc[nt][2] * ad0 + acc[nt][3] * ad1;
    }
    // reduce over the 4-lane group (t = 0..3)
#pragma unroll
    for (int i = 0; i < 8; i++) {
        vs0[i] += __shfl_xor_sync(0xffffffffu, vs0[i], 1);
        vs0[i] += __shfl_xor_sync(0xffffffffu, vs0[i], 2);
        vd0[i] += __shfl_xor_sync(0xffffffffu, vd0[i], 1);
        vd0[i] += __shfl_xor_sync(0xffffffffu, vd0[i], 2);
        vs1[i] += __shfl_xor_sync(0xffffffffu, vs1[i], 1);
        vs1[i] += __shfl_xor_sync(0xffffffffu, vs1[i], 2);
        vd1[i] += __shfl_xor_sync(0xffffffffu, vd1[i], 1);
        vd1[i] += __shfl_xor_sync(0xffffffffu, vd1[i], 2);
    }
    if (t == 0) {
        if (ok0) {
            *(float4*)&g_asrc[(size_t)r0 * HH]     = make_float4(vs0[0], vs0[1], vs0[2], vs0[3]);
            *(float4*)&g_asrc[(size_t)r0 * HH + 4] = make_float4(vs0[4], vs0[5], vs0[6], vs0[7]);
            *(float4*)&g_adst[(size_t)r0 * HH]     = make_float4(vd0[0], vd0[1], vd0[2], vd0[3]);
            *(float4*)&g_adst[(size_t)r0 * HH + 4] = make_float4(vd0[4], vd0[5], vd0[6], vd0[7]);
        }
        if (ok1) {
            *(float4*)&g_asrc[(size_t)r1 * HH]     = make_float4(vs1[0], vs1[1], vs1[2], vs1[3]);
            *(float4*)&g_asrc[(size_t)r1 * HH + 4] = make_float4(vs1[4], vs1[5], vs1[6], vs1[7]);
            *(float4*)&g_adst[(size_t)r1 * HH]     = make_float4(vd1[0], vd1[1], vd1[2], vd1[3]);
            *(float4*)&g_adst[(size_t)r1 * HH + 4] = make_float4(vd1[4], vd1[5], vd1[6], vd1[7]);
        }
    }
}

// ---------------------------------------------------------------------------
// CSR build (unchanged, R8/R9-proven)
// ---------------------------------------------------------------------------
__global__ void zerocnt_kernel(int n) {
    int i = blockIdx.x * blockDim.x + threadIdx.x;
    if (i <= n) g_cnt[i] = 0;
}

__global__ void hist_kernel(const int* __restrict__ ei, int E) {
    int t = blockIdx.x * blockDim.x + threadIdx.x;
    int e = t * 2;
    if (e + 1 < E) {
        int2 d = *(const int2*)&ei[E + e];
        atomicAdd(&g_cnt[d.x], 1);
        atomicAdd(&g_cnt[d.y], 1);
    } else if (e < E) {
        atomicAdd(&g_cnt[ei[E + e]], 1);
    }
}

__global__ void scan1_kernel(int n) {
    const int i = blockIdx.x * SB + threadIdx.x;
    const int lane = threadIdx.x & 31, wid = threadIdx.x >> 5;
    int v = (i < n) ? g_cnt[i] : 0;
    int x = v;
#pragma unroll
    for (int off = 1; off < 32; off <<= 1) {
        int y = __shfl_up_sync(0xffffffffu, x, off);
        if (lane >= off) x += y;
    }
    __shared__ int ws[32];
    if (lane == 31) ws[wid] = x;
    __syncthreads();
    if (wid == 0) {
        int s = ws[lane];
#pragma unroll
        for (int off = 1; off < 32; off <<= 1) {
            int y = __shfl_up_sync(0xffffffffu, s, off);
            if (lane >= off) s += y;
        }
        ws[lane] = s;
    }
    __syncthreads();
    int excl = x - v + (wid ? ws[wid - 1] : 0);
    if (i <= n) g_rowstart[i] = excl;
    if (threadIdx.x == SB - 1) g_bsum[blockIdx.x] = excl + v;
}

__global__ void scan2_kernel(int nb) {
    const int lane = threadIdx.x;
    int v0 = (lane < nb) ? g_bsum[lane] : 0;
    int v1 = (lane + 32 < nb) ? g_bsum[lane + 32] : 0;
    int x0 = v0;
#pragma unroll
    for (int off = 1; off < 32; off <<= 1) {
        int y = __shfl_up_sync(0xffffffffu, x0, off);
        if (lane >= off) x0 += y;
    }
    int tot0 = __shfl_sync(0xffffffffu, x0, 31);
    int x1 = v1;
#pragma unroll
    for (int off = 1; off < 32; off <<= 1) {
        int y = __shfl_up_sync(0xffffffffu, x1, off);
        if (lane >= off) x1 += y;
    }
    if (lane < nb)      g_bsum[lane]      = x0 - v0;
    if (lane + 32 < nb) g_bsum[lane + 32] = tot0 + x1 - v1;
}

__global__ void scan3_kernel(int n) {
    int i = blockIdx.x * SB + threadIdx.x;
    if (i <= n) {
        int v = g_rowstart[i] + g_bsum[blockIdx.x];
        g_rowstart[i] = v;
        if (i < n) g_cursor[i] = v;
    }
}

__global__ void scatter_kernel(const int* __restrict__ ei, int E) {
    int t = blockIdx.x * blockDim.x + threadIdx.x;
    int e = t * 2;
    if (e + 1 < E) {
        int2 s = *(const int2*)&ei[e];
        int2 d = *(const int2*)&ei[E + e];
        int p0 = atomicAdd(&g_cursor[d.x], 1);
        int p1 = atomicAdd(&g_cursor[d.y], 1);
        g_csr[p0] = s.x;
        g_csr[p1] = s.y;
    } else if (e < E) {
        int d = ei[E + e];
        int p = atomicAdd(&g_cursor[d], 1);
        g_csr[p] = ei[e];
    }
}

// ---------------------------------------------------------------------------
// Fused aggregate + softmax-normalize + bias + LayerNorm (unchanged).
// ---------------------------------------------------------------------------
__global__ void agg_kernel(const float* __restrict__ bias,
                           const float* __restrict__ gamma,
                           const float* __restrict__ beta,
                           float* __restrict__ out, int n) {
    const int wrp = (blockIdx.x * blockDim.x + threadIdx.x) >> 5;
    if (wrp >= n) return;
    const int lane = threadIdx.x & 31;
    const int h = lane >> 2;

    const int row = g_rowstart[wrp];
    const int end = g_rowstart[wrp + 1];
    const float adh = g_adst[(size_t)wrp * HH + h];
    const float4* __restrict__ xp4 = (const float4*)g_xp;

    float4 acc = make_float4(0.f, 0.f, 0.f, 0.f);
    float wsum = 0.f;

    int i = row;
    for (; i + 1 < end; i += 2) {
        int s0 = g_csr[i];
        int s1 = g_csr[i + 1];
        float a0 = g_asrc[(size_t)s0 * HH + h];
        float a1 = g_asrc[(size_t)s1 * HH + h];
        float4 x0 = xp4[(size_t)s0 * 32 + lane];
        float4 x1 = xp4[(size_t)s1 * 32 + lane];
        float v0 = a0 + adh; v0 = v0 > 0.f ? v0 : 0.2f * v0;
        float v1 = a1 + adh; v1 = v1 > 0.f ? v1 : 0.2f * v1;
        float w0 = __expf(v0);
        float w1 = __expf(v1);
        acc.x = fmaf(w0, x0.x, acc.x); acc.y = fmaf(w0, x0.y, acc.y);
        acc.z = fmaf(w0, x0.z, acc.z); acc.w = fmaf(w0, x0.w, acc.w);
        acc.x = fmaf(w1, x1.x, acc.x); acc.y = fmaf(w1, x1.y, acc.y);
        acc.z = fmaf(w1, x1.z, acc.z); acc.w = fmaf(w1, x1.w, acc.w);
        wsum += w0 + w1;
    }
    if (i < end) {
        int s = g_csr[i];
        float v = g_asrc[(size_t)s * HH + h] + adh;
        v = v > 0.f ? v : 0.2f * v;
        float wgt = __expf(v);
        float4 xv = xp4[(size_t)s * 32 + lane];
        acc.x = fmaf(wgt, xv.x, acc.x); acc.y = fmaf(wgt, xv.y, acc.y);
        acc.z = fmaf(wgt, xv.z, acc.z); acc.w = fmaf(wgt, xv.w, acc.w);
        wsum += wgt;
    }
    {
        float v = g_asrc[(size_t)wrp * HH + h] + adh;
        v = v > 0.f ? v : 0.2f * v;
        float wgt = __expf(v);
        float4 xv = xp4[(size_t)wrp * 32 + lane];
        acc.x = fmaf(wgt, xv.x, acc.x); acc.y = fmaf(wgt, xv.y, acc.y);
        acc.z = fmaf(wgt, xv.z, acc.z); acc.w = fmaf(wgt, xv.w, acc.w);
        wsum += wgt;
    }

    const float inv_w = 1.f / wsum;
    float4 b4 = ((const float4*)bias)[lane];
    float4 o;
    o.x = acc.x * inv_w + b4.x;
    o.y = acc.y * inv_w + b4.y;
    o.z = acc.z * inv_w + b4.z;
    o.w = acc.w * inv_w + b4.w;

    float s1 = o.x + o.y + o.z + o.w;
    float s2 = o.x * o.x + o.y * o.y + o.z * o.z + o.w * o.w;
#pragma unroll
    for (int off = 16; off; off >>= 1) {
        s1 += __shfl_xor_sync(0xffffffffu, s1, off);
        s2 += __shfl_xor_sync(0xffffffffu, s2, off);
    }
    float mu  = s1 * (1.f / 128.f);
    float var = s2 * (1.f / 128.f) - mu * mu;
    float inv = rsqrtf(var + 1e-5f);

    float4 g4 = ((const float4*)gamma)[lane];
    float4 e4 = ((const float4*)beta)[lane];
    float4 r;
    r.x = (o.x - mu) * inv * g4.x + e4.x;
    r.y = (o.y - mu) * inv * g4.y + e4.y;
    r.z = (o.z - mu) * inv * g4.z + e4.z;
    r.w = (o.w - mu) * inv * g4.w + e4.w;
    ((float4*)out)[(size_t)wrp * 32 + lane] = r;
}

// ---------------------------------------------------------------------------
extern "C" void kernel_launch(void* const* d_in, const int* in_sizes, int n_in,
                              void* d_out, int out_size) {
    const float* x       = (const float*)d_in[0];
    const int*   ei      = (const int*)d_in[1];
    const float* W       = (const float*)d_in[2];
    const float* att_src = (const float*)d_in[3];
    const float* att_dst = (const float*)d_in[4];
    const float* bias    = (const float*)d_in[5];
    const float* gamma   = (const float*)d_in[6];
    const float* beta    = (const float*)d_in[7];
    float* out = (float*)d_out;

    const int n = in_sizes[0] / FD;   // 50000
    const int E = in_sizes[1] / 2;    // 800000
    const int nb = (n + 1 + SB - 1) / SB;

    wfrag_prep<<<16, 256>>>(W);                                       // 0
    zerocnt_kernel<<<(n + 1 + 255) / 256, 256>>>(n);                  // 1
    hist_kernel<<<((E + 1) / 2 + 255) / 256, 256>>>(ei, E);           // 2
    gemm_mma<<<(n + TMR - 1) / TMR, 256>>>(x, att_src, att_dst, n);   // 3 (profiler slot)
    scan1_kernel<<<nb, SB>>>(n);                                      // 4
    scan2_kernel<<<1, 32>>>(nb);                                      // 5
    scan3_kernel<<<nb, SB>>>(n);                                      // 6
    scatter_kernel<<<((E + 1) / 2 + 255) / 256, 256>>>(ei, E);        // 7
    agg_kernel<<<(n * 32 + 255) / 256, 256>>>(bias, gamma, beta, out, n); // 8
}